// round 5
// baseline (speedup 1.0000x reference)
#include <cuda_runtime.h>
#include <cuda_bf16.h>
#include <cstdint>
#include <cstddef>

// ---------------------------------------------------------------------------
// Problem dims
// ---------------------------------------------------------------------------
#define BATCH 8192
#define INF   784
#define KPAD  832          // 13 * 64 (chunk 12 holds only 16 valid K)
#define HID   4096
#define OUTD  10

#define BM 128             // CTA M tile
#define BN 256             // CTA N tile
#define BK 64
#define NCHUNK 13
#define NTIL   (HID / BN)  // 16 n-tiles
#define NSLAB  (NTIL * 2)  // 32 partial slabs

// ---------------------------------------------------------------------------
// Device scratch (static -> no allocations)
// ---------------------------------------------------------------------------
__device__ __nv_bfloat16 g_xhi[(size_t)BATCH * KPAD];
__device__ __nv_bfloat16 g_xlo[(size_t)BATCH * KPAD];
__device__ __nv_bfloat16 g_wb [(size_t)HID   * KPAD];
__device__ float g_part[(size_t)NSLAB * BATCH * OUTD];   // 10.5 MB

// ---------------------------------------------------------------------------
// PTX helpers (sm_80-class; valid at compute_100)
// ---------------------------------------------------------------------------
__device__ __forceinline__ uint32_t smem_u32(const void* p) {
    uint32_t a;
    asm("{ .reg .u64 t; cvta.to.shared.u64 t, %1; cvt.u32.u64 %0, t; }"
        : "=r"(a) : "l"(p));
    return a;
}
__device__ __forceinline__ void cp16(uint32_t saddr, const void* gaddr) {
    asm volatile("cp.async.cg.shared.global [%0], [%1], 16;"
                 :: "r"(saddr), "l"(gaddr) : "memory");
}
__device__ __forceinline__ void cp_commit() {
    asm volatile("cp.async.commit_group;" ::: "memory");
}
__device__ __forceinline__ void cp_wait2() {
    asm volatile("cp.async.wait_group 2;" ::: "memory");
}
__device__ __forceinline__ void cp_wait0() {
    asm volatile("cp.async.wait_group 0;" ::: "memory");
}
__device__ __forceinline__ void ldsm4(uint32_t& r0, uint32_t& r1,
                                      uint32_t& r2, uint32_t& r3, uint32_t a) {
    asm volatile("ldmatrix.sync.aligned.m8n8.x4.shared.b16 {%0,%1,%2,%3}, [%4];"
                 : "=r"(r0), "=r"(r1), "=r"(r2), "=r"(r3) : "r"(a));
}
__device__ __forceinline__ void mma16816(float* c, const uint32_t* a, const uint32_t* b) {
    asm volatile(
        "mma.sync.aligned.m16n8k16.row.col.f32.bf16.bf16.f32 "
        "{%0,%1,%2,%3}, {%4,%5,%6,%7}, {%8,%9}, {%0,%1,%2,%3};"
        : "+f"(c[0]), "+f"(c[1]), "+f"(c[2]), "+f"(c[3])
        : "r"(a[0]), "r"(a[1]), "r"(a[2]), "r"(a[3]), "r"(b[0]), "r"(b[1]));
}

// ---------------------------------------------------------------------------
// Dynamic SMEM layout
//   [0,1024)        b1 slice (256 f32)
//   [1024,13312)    W2^T slice: 256 cols x 12 f32 (10 used, padded)
//   [16384,...)     3 stages x { Ahi 16K | Alo 16K | B 32K } = 64K each
// ---------------------------------------------------------------------------
#define SM_B1      0
#define SM_W2V     1024
#define SM_STAGE0  16384
#define STAGE_SZ   65536
#define OFF_ALO    16384
#define OFF_B      32768
#define SMEM_TOTAL (SM_STAGE0 + 3 * STAGE_SZ)   // 212992 B -> 1 CTA/SM

// ---------------------------------------------------------------------------
// prep kernels
// ---------------------------------------------------------------------------
__global__ __launch_bounds__(256) void prep_x(const float* __restrict__ X) {
    int idx = blockIdx.x * 256 + threadIdx.x;
    int m   = idx / (KPAD / 4);
    int k4  = (idx - m * (KPAD / 4)) * 4;
    if (m >= BATCH) return;
    __nv_bfloat16 hi[4], lo[4];
    if (k4 < INF) {
        const float4 v = *(const float4*)&X[(size_t)m * INF + k4];
        const float vv[4] = {v.x, v.y, v.z, v.w};
        #pragma unroll
        for (int e = 0; e < 4; e++) {
            hi[e] = __float2bfloat16(vv[e]);
            lo[e] = __float2bfloat16(vv[e] - __bfloat162float(hi[e]));
        }
    } else {
        #pragma unroll
        for (int e = 0; e < 4; e++) { hi[e] = __float2bfloat16(0.f); lo[e] = hi[e]; }
    }
    *(uint2*)&g_xhi[(size_t)m * KPAD + k4] = *(uint2*)hi;
    *(uint2*)&g_xlo[(size_t)m * KPAD + k4] = *(uint2*)lo;
}

__global__ __launch_bounds__(256) void prep_w(const float* __restrict__ W1) {
    int idx = blockIdx.x * 256 + threadIdx.x;
    int n   = idx / (KPAD / 4);
    int k4  = (idx - n * (KPAD / 4)) * 4;
    if (n >= HID) return;
    __nv_bfloat16 s[4];
    if (k4 < INF) {
        const float4 v = *(const float4*)&W1[(size_t)n * INF + k4];
        const float vv[4] = {v.x, v.y, v.z, v.w};
        #pragma unroll
        for (int e = 0; e < 4; e++) {
            float sv = (vv[e] > 0.f) ? 1.f : ((vv[e] < 0.f) ? -1.f : 0.f);
            s[e] = __float2bfloat16(sv);
        }
    } else {
        #pragma unroll
        for (int e = 0; e < 4; e++) s[e] = __float2bfloat16(0.f);
    }
    *(uint2*)&g_wb[(size_t)n * KPAD + k4] = *(uint2*)s;
}

// ---------------------------------------------------------------------------
// fc1 (bf16 hi/lo tensor-core GEMM) + fused fc2 partial
//   CTA tile 128x256, 8 warps as 4(M)x2(N) of 32x128 warp tiles, 3-stage pipe
// ---------------------------------------------------------------------------
__global__ __launch_bounds__(256, 1) void fc1_mma(const float* __restrict__ b1,
                                                  const float* __restrict__ W2)
{
    extern __shared__ char smem[];
    const uint32_t sb = smem_u32(smem);
    const int tid  = threadIdx.x;
    const int warp = tid >> 5;
    const int lane = tid & 31;
    const int wm   = warp >> 1;      // 0..3 -> m offset 32*wm
    const int wn   = warp & 1;       // 0..1 -> n offset 128*wn
    const int bn   = blockIdx.x * BN;
    const int bm   = blockIdx.y * BM;

    const char* xh = (const char*)g_xhi + (size_t)bm * (KPAD * 2);
    const char* xl = (const char*)g_xlo + (size_t)bm * (KPAD * 2);
    const char* wb = (const char*)g_wb  + (size_t)bn * (KPAD * 2);

    const int ldrow = tid >> 3;             // 0..31
    const int ldub  = (tid & 7) * 16;       // byte within 128B row

    // issue cp.async for chunk c into stage c%3 (chunk 12: only valid 32B/row)
    auto issue = [&](int c) {
        const uint32_t sbase = sb + SM_STAGE0 + (uint32_t)(c % 3) * STAGE_SZ;
        const size_t kb = (size_t)c * 128;
        if (c < 12 || ldub < 32) {
            #pragma unroll
            for (int r = 0; r < 4; r++) {            // A_hi / A_lo: 128 rows
                const int row = ldrow + 32 * r;
                const uint32_t so = (uint32_t)(row * 128 + (ldub ^ ((row & 7) << 4)));
                const size_t  go = (size_t)row * (KPAD * 2) + kb + ldub;
                cp16(sbase + so,           xh + go);
                cp16(sbase + OFF_ALO + so, xl + go);
            }
            #pragma unroll
            for (int r = 0; r < 8; r++) {            // B: 256 rows
                const int row = ldrow + 32 * r;
                const uint32_t so = (uint32_t)(row * 128 + (ldub ^ ((row & 7) << 4)));
                const size_t  go = (size_t)row * (KPAD * 2) + kb + ldub;
                cp16(sbase + OFF_B + so, wb + go);
            }
        }
    };

    // ---- prologue ----
    issue(0); cp_commit();
    issue(1); cp_commit();
    {
        float* b1s = (float*)(smem + SM_B1);
        float* w2v = (float*)(smem + SM_W2V);
        for (int i = tid; i < BN; i += 256) b1s[i] = b1[bn + i];
        for (int i = tid; i < BN * 12; i += 256) {
            int col = i / 12, o = i - col * 12;
            w2v[i] = (o < OUTD) ? W2[(size_t)o * HID + bn + col] : 0.f;
        }
    }

    // ldmatrix per-lane address components
    const int xl4   = (lane & 7) << 4;
    const int arow  = (lane & 7) + 8 * ((lane >> 3) & 1);
    const int akb   = (lane >> 4) * 16;
    const int brow  = (lane & 7) + 8 * (lane >> 4);
    const int bkb   = ((lane >> 3) & 1) * 16;

    float acc[2][16][4];
    #pragma unroll
    for (int mi = 0; mi < 2; mi++)
        #pragma unroll
        for (int ni = 0; ni < 16; ni++)
            #pragma unroll
            for (int j = 0; j < 4; j++) acc[mi][ni][j] = 0.f;

    // one K=32 step (two k16 slices per ldsm) at column-offset ko
    auto mma_step = [&](uint32_t sA, uint32_t sAl, uint32_t sB, int ko) {
        uint32_t ah[2][4], al[2][4], bf[16][2];
        #pragma unroll
        for (int mi = 0; mi < 2; mi++) {
            const int row = wm * 32 + mi * 16 + arow;
            const uint32_t off = (uint32_t)(row * 128 + ((ko + akb) ^ xl4));
            ldsm4(ah[mi][0], ah[mi][1], ah[mi][2], ah[mi][3], sA + off);
            ldsm4(al[mi][0], al[mi][1], al[mi][2], al[mi][3], sAl + off);
        }
        #pragma unroll
        for (int nj = 0; nj < 8; nj++) {
            const int row = wn * 128 + nj * 16 + brow;
            const uint32_t off = (uint32_t)(row * 128 + ((ko + bkb) ^ xl4));
            ldsm4(bf[2 * nj][0], bf[2 * nj][1], bf[2 * nj + 1][0], bf[2 * nj + 1][1],
                  sB + off);
        }
        #pragma unroll
        for (int mi = 0; mi < 2; mi++)
            #pragma unroll
            for (int ni = 0; ni < 16; ni++) {
                mma16816(acc[mi][ni], ah[mi], bf[ni]);
                mma16816(acc[mi][ni], al[mi], bf[ni]);
            }
    };

    // ---- mainloop: chunks 0..11 (full 64-K), 3-stage pipeline ----
    for (int c = 0; c < 12; c++) {
        if (c + 2 < NCHUNK) issue(c + 2);
        cp_commit();                 // always commit (possibly empty group)
        cp_wait2();                  // chunk c's group complete
        __syncthreads();

        const uint32_t sA  = sb + SM_STAGE0 + (uint32_t)(c % 3) * STAGE_SZ;
        const uint32_t sAl = sA + OFF_ALO;
        const uint32_t sB  = sA + OFF_B;
        mma_step(sA, sAl, sB, 0);
        mma_step(sA, sAl, sB, 32);
        mma_step(sA, sAl, sB, 64);
        mma_step(sA, sAl, sB, 96);
        __syncthreads();
    }
    // ---- tail chunk 12: only 16 valid K -> single ks step ----
    {
        cp_wait0();
        __syncthreads();
        const uint32_t sA  = sb + SM_STAGE0 + (uint32_t)(12 % 3) * STAGE_SZ;
        mma_step(sA, sA + OFF_ALO, sA + OFF_B, 0);
    }

    // ---- epilogue: +b1, hardtanh, fused fc2 partial ----
    const float*  b1s  = (const float*)(smem + SM_B1);
    const float4* w2v4 = (const float4*)(smem + SM_W2V);

    float acco[2][2][OUTD];
    #pragma unroll
    for (int mi = 0; mi < 2; mi++)
        #pragma unroll
        for (int jh = 0; jh < 2; jh++)
            #pragma unroll
            for (int o = 0; o < OUTD; o++) acco[mi][jh][o] = 0.f;

    #pragma unroll
    for (int ni = 0; ni < 16; ni++) {
        #pragma unroll
        for (int jl = 0; jl < 2; jl++) {
            const int ncol = wn * 128 + ni * 8 + 2 * (lane & 3) + jl;
            const float bias = b1s[ncol];
            const float4 w0  = w2v4[ncol * 3 + 0];
            const float4 w1  = w2v4[ncol * 3 + 1];
            const float4 w2_ = w2v4[ncol * 3 + 2];
            #pragma unroll
            for (int mi = 0; mi < 2; mi++) {
                #pragma unroll
                for (int jh = 0; jh < 2; jh++) {
                    float hv = acc[mi][ni][jh * 2 + jl] + bias;
                    hv = fminf(fmaxf(hv, -1.f), 1.f);
                    acco[mi][jh][0] += hv * w0.x;  acco[mi][jh][1] += hv * w0.y;
                    acco[mi][jh][2] += hv * w0.z;  acco[mi][jh][3] += hv * w0.w;
                    acco[mi][jh][4] += hv * w1.x;  acco[mi][jh][5] += hv * w1.y;
                    acco[mi][jh][6] += hv * w1.z;  acco[mi][jh][7] += hv * w1.w;
                    acco[mi][jh][8] += hv * w2_.x; acco[mi][jh][9] += hv * w2_.y;
                }
            }
        }
    }

    // quad-lane reduction (lanes of a quad hold distinct n cols)
    #pragma unroll
    for (int mi = 0; mi < 2; mi++)
        #pragma unroll
        for (int jh = 0; jh < 2; jh++)
            #pragma unroll
            for (int o = 0; o < OUTD; o++) {
                float v = acco[mi][jh][o];
                v += __shfl_xor_sync(0xffffffffu, v, 1);
                v += __shfl_xor_sync(0xffffffffu, v, 2);
                acco[mi][jh][o] = v;
            }

    if ((lane & 3) == 0) {
        const size_t slab = (size_t)(blockIdx.x * 2 + wn);
        #pragma unroll
        for (int mi = 0; mi < 2; mi++)
            #pragma unroll
            for (int jh = 0; jh < 2; jh++) {
                const int row = bm + wm * 32 + mi * 16 + (lane >> 2) + 8 * jh;
                float* dst = g_part + (slab * BATCH + row) * OUTD;
                #pragma unroll
                for (int o = 0; o < OUTD; o++) dst[o] = acco[mi][jh][o];
            }
    }
}

// ---------------------------------------------------------------------------
// reduce: out[m][o] = b2[o] + sum_p g_part[p][m][o]
// ---------------------------------------------------------------------------
__global__ __launch_bounds__(256) void reduce_out(const float* __restrict__ b2,
                                                  float* __restrict__ out)
{
    const int idx = blockIdx.x * 256 + threadIdx.x;
    if (idx >= BATCH * OUTD) return;
    const int o = idx % OUTD;
    float s = b2[o];
    #pragma unroll
    for (int p = 0; p < NSLAB; p++)
        s += g_part[(size_t)p * (BATCH * OUTD) + idx];
    out[idx] = s;
}

// ---------------------------------------------------------------------------
// Launch
// ---------------------------------------------------------------------------
extern "C" void kernel_launch(void* const* d_in, const int* in_sizes, int n_in,
                              void* d_out, int out_size)
{
    const float* X  = (const float*)d_in[0];
    const float* W1 = (const float*)d_in[1];
    const float* b1 = (const float*)d_in[2];
    const float* W2 = (const float*)d_in[3];
    const float* b2 = (const float*)d_in[4];
    float* out = (float*)d_out;

    cudaFuncSetAttribute(fc1_mma, cudaFuncAttributeMaxDynamicSharedMemorySize, SMEM_TOTAL);

    prep_x<<<(BATCH * (KPAD / 4)) / 256, 256>>>(X);
    prep_w<<<(HID   * (KPAD / 4)) / 256, 256>>>(W1);

    dim3 grid1(NTIL, BATCH / BM);   // 16 x 64
    fc1_mma<<<grid1, 256, SMEM_TOTAL>>>(b1, W2);

    reduce_out<<<(BATCH * OUTD + 255) / 256, 256>>>(b2, out);
}